// round 15
// baseline (speedup 1.0000x reference)
#include <cuda_runtime.h>
#include <cuda_fp16.h>
#include <cstdint>
#include <cstddef>

// ---------------------------------------------------------------------------
// CrossAttention_41497974014052  (sm_103a, legacy mma path)
// K0: W fp32 -> half pre-convert
// K1: depthwise3x3 (smem-tiled, 32-row tiles, half2 stores)
// K2: pointwise GEMM, CTA tile 256x64 (y read ONCE), fp16 m16n8k16,
//     cp.async 3-stage, ldmatrix frags, 2 CTAs/SM
// K3: per-(b,h) channel attention, FA2-style (unchanged from R13)
// ---------------------------------------------------------------------------

constexpr int Bn = 8, Cn = 256, Hn = 128, Wn = 128;
constexpr int HWn = Hn * Wn;                    // 16384
constexpr size_t CHWn = (size_t)Cn * HWn;       // 4194304
constexpr size_t IMG  = (size_t)Bn * CHWn;      // 33554432

__device__ __half g_y[3 * IMG];
__device__ __half g_qkv[3 * IMG];
__device__ __half g_wh[3 * 65536];

__device__ __forceinline__ uint32_t f2h2(float a, float b) {
    __half2 h = __floats2half2_rn(a, b);
    return *reinterpret_cast<uint32_t*>(&h);
}
__device__ __forceinline__ uint32_t smem_u32(const void* p) {
    uint32_t a;
    asm("{ .reg .u64 t; cvta.to.shared.u64 t, %1; cvt.u32.u64 %0, t; }" : "=r"(a) : "l"(p));
    return a;
}
__device__ __forceinline__ void mma16(float d[4], const uint32_t a[4], const uint32_t b[2]) {
    asm volatile(
        "mma.sync.aligned.m16n8k16.row.col.f32.f16.f16.f32 "
        "{%0,%1,%2,%3}, {%4,%5,%6,%7}, {%8,%9}, {%0,%1,%2,%3};\n"
        : "+f"(d[0]), "+f"(d[1]), "+f"(d[2]), "+f"(d[3])
        : "r"(a[0]), "r"(a[1]), "r"(a[2]), "r"(a[3]), "r"(b[0]), "r"(b[1]));
}
__device__ __forceinline__ void ldsm4(uint32_t& r0, uint32_t& r1, uint32_t& r2, uint32_t& r3,
                                      uint32_t addr) {
    asm volatile("ldmatrix.sync.aligned.m8n8.x4.shared.b16 {%0,%1,%2,%3}, [%4];"
                 : "=r"(r0), "=r"(r1), "=r"(r2), "=r"(r3) : "r"(addr));
}
__device__ __forceinline__ void ldsm4t(uint32_t& r0, uint32_t& r1, uint32_t& r2, uint32_t& r3,
                                       uint32_t addr) {
    asm volatile("ldmatrix.sync.aligned.m8n8.x4.trans.shared.b16 {%0,%1,%2,%3}, [%4];"
                 : "=r"(r0), "=r"(r1), "=r"(r2), "=r"(r3) : "r"(addr));
}
__device__ __forceinline__ void cp16(uint32_t dst, const void* src) {
    asm volatile("cp.async.cg.shared.global [%0], [%1], 16;"
                 :: "r"(dst), "l"((size_t)__cvta_generic_to_global(src)) : "memory");
}
#define CP_COMMIT() asm volatile("cp.async.commit_group;" ::: "memory")
#define CP_WAIT1()  asm volatile("cp.async.wait_group 1;" ::: "memory")
#define CP_WAIT0()  asm volatile("cp.async.wait_group 0;" ::: "memory")

// ---------------------------------------------------------------------------
// Kernel 0: W fp32 -> half. grid (128, 3), 256 thr.
// ---------------------------------------------------------------------------
__global__ void k_wconv(const float* __restrict__ qpw, const float* __restrict__ kpw,
                        const float* __restrict__ vpw)
{
    int t = blockIdx.y;
    const float* W = (t == 0) ? qpw : (t == 1) ? kpw : vpw;
    int i = (blockIdx.x * 256 + threadIdx.x) * 2;
    float2 v = *(const float2*)(W + i);
    *(__half2*)(g_wh + t * 65536 + i) = __floats2half2_rn(v.x, v.y);
}

// ---------------------------------------------------------------------------
// Kernel 1: depthwise 3x3 (SAME) + bias, smem-tiled, 32-row tiles,
// 2 cols/thread (half2 out). grid (H/32, B*C), 256 threads.
// ---------------------------------------------------------------------------
__global__ void __launch_bounds__(256)
k_dwconv(const float* __restrict__ hidden, const float* __restrict__ ctx,
         const float* __restrict__ qw, const float* __restrict__ qb,
         const float* __restrict__ kw, const float* __restrict__ kb,
         const float* __restrict__ vw, const float* __restrict__ vb)
{
    __shared__ float shH[34][132];
    __shared__ float shC[34][132];

    int h0 = blockIdx.x * 32;
    int bc = blockIdx.y;
    int c  = bc & (Cn - 1);
    int tid = threadIdx.x;
    size_t base = (size_t)bc * HWn;
    const float* xh = hidden + base;
    const float* xc = ctx + base;

    for (int idx = tid; idx < 34 * 130; idx += 256) {
        int r = idx / 130, ci = idx - r * 130;
        int hh = h0 + r - 1, ww = ci - 1;
        bool ok = ((unsigned)hh < (unsigned)Hn) & ((unsigned)ww < (unsigned)Wn);
        float vh = 0.f, vc = 0.f;
        if (ok) { int o = hh * Wn + ww; vh = xh[o]; vc = xc[o]; }
        shH[r][ci] = vh;
        shC[r][ci] = vc;
    }

    float wq[9], wk[9], wv[9];
    #pragma unroll
    for (int i = 0; i < 9; i++) {
        wq[i] = qw[c * 9 + i]; wk[i] = kw[c * 9 + i]; wv[i] = vw[c * 9 + i];
    }
    float bq = qb[c], bk = kb[c], bv = vb[c];
    __syncthreads();

    int w2 = (tid & 63) * 2;
    int rb = (tid >> 6) * 8;          // 4 groups x 8 rows = 32 rows

    float A0[4], A1[4], A2[4], B0[4], B1[4], B2[4];
    #pragma unroll
    for (int j = 0; j < 4; j++) {
        A0[j] = shH[rb][w2 + j];     A1[j] = shH[rb + 1][w2 + j];
        B0[j] = shC[rb][w2 + j];     B1[j] = shC[rb + 1][w2 + j];
    }

    #pragma unroll
    for (int rr = 0; rr < 8; rr++) {
        #pragma unroll
        for (int j = 0; j < 4; j++) {
            A2[j] = shH[rb + rr + 2][w2 + j];
            B2[j] = shC[rb + rr + 2][w2 + j];
        }
        float aq0 = bq, aq1 = bq, ak0 = bk, ak1 = bk, av0 = bv, av1 = bv;
        #pragma unroll
        for (int j = 0; j < 3; j++) {
            aq0 += wq[j] * A0[j]     + wq[3 + j] * A1[j]     + wq[6 + j] * A2[j];
            aq1 += wq[j] * A0[j + 1] + wq[3 + j] * A1[j + 1] + wq[6 + j] * A2[j + 1];
            ak0 += wk[j] * B0[j]     + wk[3 + j] * B1[j]     + wk[6 + j] * B2[j];
            ak1 += wk[j] * B0[j + 1] + wk[3 + j] * B1[j + 1] + wk[6 + j] * B2[j + 1];
            av0 += wv[j] * B0[j]     + wv[3 + j] * B1[j]     + wv[6 + j] * B2[j];
            av1 += wv[j] * B0[j + 1] + wv[3 + j] * B1[j + 1] + wv[6 + j] * B2[j + 1];
        }
        size_t o = base + (size_t)(h0 + rb + rr) * Wn + w2;
        *(__half2*)(g_y + o)           = __floats2half2_rn(aq0, aq1);
        *(__half2*)(g_y + IMG + o)     = __floats2half2_rn(ak0, ak1);
        *(__half2*)(g_y + 2 * IMG + o) = __floats2half2_rn(av0, av1);
        #pragma unroll
        for (int j = 0; j < 4; j++) {
            A0[j] = A1[j]; A1[j] = A2[j];
            B0[j] = B1[j]; B1[j] = B2[j];
        }
    }
}

// ---------------------------------------------------------------------------
// Kernel 2: pointwise GEMM  D[o][s] = sum_c W[o][c] * y[c][s] + bias[o]
// CTA tile 256(M) x 64(N): y streamed ONCE (B operand), W from L2.
// fp16 m16n8k16, K=256 in 8 chunks of 32, cp.async 3-stage, ldmatrix frags.
// 256 thr = 8 warps (4M x 2N), warp tile 64x32, 2 CTAs/SM.
// q output (t==0) pre-scaled by 1/sqrt(32).
// grid (256, 24)
// ---------------------------------------------------------------------------
constexpr int PW_AS_STRIDE = 256 * 40 * 2;   // 20480
constexpr int PW_BS_BASE   = 3 * PW_AS_STRIDE;             // 61440
constexpr int PW_BS_STRIDE = 32 * 72 * 2;    // 4608
constexpr int PW_SMEM      = PW_BS_BASE + 3 * PW_BS_STRIDE; // 75264

__global__ void __launch_bounds__(256, 2)
k_pointwise(const float* __restrict__ qpb, const float* __restrict__ kpb,
            const float* __restrict__ vpb)
{
    extern __shared__ __align__(16) char dyn[];
    uint32_t sb = smem_u32(dyn);

    int nt = blockIdx.x, tb = blockIdx.y;
    int t = tb >> 3, b = tb & 7;
    const float* bias = (t == 0) ? qpb : (t == 1) ? kpb : vpb;
    const float oscale = (t == 0) ? 0.17677669529663687f : 1.0f;
    const __half* Wh = g_wh + t * 65536;
    const __half* Yt = g_y  + (size_t)t * IMG + (size_t)b * CHWn;
    __half*       Cm = g_qkv + (size_t)t * IMG + (size_t)b * CHWn;
    int n0 = nt * 64;

    int tid = threadIdx.x, lane = tid & 31, warp = tid >> 5;
    int wm = warp >> 1, wn = warp & 1, g = lane >> 2, tg = lane & 3;

    int rA = tid >> 1, cA = (tid & 1) * 16;   // A: rows rA, rA+128; 32 k-cols
    int rB = tid >> 3, cB = (tid & 7) * 8;    // B: 32 x 64

    int aRow = wm * 64 + (lane & 15);
    int aKoff = (lane >> 4) * 8;

    auto issue = [&](int stage) {
        int buf = stage % 3;
        int k0 = stage * 32;
        uint32_t asb = sb + buf * PW_AS_STRIDE;
        uint32_t bsb = sb + PW_BS_BASE + buf * PW_BS_STRIDE;
        const __half* srcA0 = Wh + (size_t)rA * Cn + k0 + cA;
        const __half* srcA1 = Wh + (size_t)(rA + 128) * Cn + k0 + cA;
        cp16(asb + (rA * 40 + cA) * 2, srcA0);
        cp16(asb + (rA * 40 + cA + 8) * 2, srcA0 + 8);
        cp16(asb + ((rA + 128) * 40 + cA) * 2, srcA1);
        cp16(asb + ((rA + 128) * 40 + cA + 8) * 2, srcA1 + 8);
        cp16(bsb + (rB * 72 + cB) * 2, Yt + (size_t)(k0 + rB) * HWn + n0 + cB);
        CP_COMMIT();
    };

    float acc[4][4][4];
    #pragma unroll
    for (int i = 0; i < 4; i++)
        #pragma unroll
        for (int j = 0; j < 4; j++)
            #pragma unroll
            for (int r = 0; r < 4; r++) acc[i][j][r] = 0.f;

    issue(0);
    issue(1);

    for (int kc = 0; kc < 8; kc++) {
        if (kc < 7) { CP_WAIT1(); } else { CP_WAIT0(); }
        __syncthreads();
        if (kc + 2 < 8) issue(kc + 2);

        int buf = kc % 3;
        uint32_t asb = sb + buf * PW_AS_STRIDE;
        uint32_t bsb = sb + PW_BS_BASE + buf * PW_BS_STRIDE;

        #pragma unroll
        for (int kk = 0; kk < 32; kk += 16) {
            uint32_t af[4][4], bfm[4][2];
            #pragma unroll
            for (int mi = 0; mi < 4; mi++)
                ldsm4(af[mi][0], af[mi][1], af[mi][2], af[mi][3],
                      asb + ((aRow + mi * 16) * 40 + kk + aKoff) * 2);
            #pragma unroll
            for (int nh = 0; nh < 2; nh++) {
                int lrow = kk + (lane & 15);
                int lcol = wn * 32 + nh * 16 + (lane >> 4) * 8;
                ldsm4t(bfm[2 * nh][0], bfm[2 * nh][1], bfm[2 * nh + 1][0], bfm[2 * nh + 1][1],
                       bsb + (lrow * 72 + lcol) * 2);
            }
            #pragma unroll
            for (int mi = 0; mi < 4; mi++)
                #pragma unroll
                for (int nb = 0; nb < 4; nb++)
                    mma16(acc[mi][nb], af[mi], bfm[nb]);
        }
    }

    #pragma unroll
    for (int mi = 0; mi < 4; mi++) {
        int m = wm * 64 + mi * 16 + g;
        float b0v = bias[m], b1v = bias[m + 8];
        #pragma unroll
        for (int nb = 0; nb < 4; nb++) {
            int n = n0 + wn * 32 + nb * 8 + tg * 2;
            *(__half2*)(Cm + (size_t)m * HWn + n) =
                __floats2half2_rn((acc[mi][nb][0] + b0v) * oscale, (acc[mi][nb][1] + b0v) * oscale);
            *(__half2*)(Cm + (size_t)(m + 8) * HWn + n) =
                __floats2half2_rn((acc[mi][nb][2] + b1v) * oscale, (acc[mi][nb][3] + b1v) * oscale);
        }
    }
}

// ---------------------------------------------------------------------------
// Kernel 3: per-(b,h) channel attention, FA2-style (unchanged from R13).
// 512 threads = 16 warps; warp w owns S-rows [16w, 16w+16).
// smem: Qs 256x136 | Ks 256x136 | Vs 256x136 (half)  = 208896 B
// ---------------------------------------------------------------------------
constexpr int K3_QS   = 0;
constexpr int K3_KS   = 256 * 136 * 2;            // 69632
constexpr int K3_VS   = 2 * 256 * 136 * 2;        // 139264
constexpr int K3_SMEM = 3 * 256 * 136 * 2;        // 208896

__global__ void __launch_bounds__(512)
k_attn(float* __restrict__ out)
{
    extern __shared__ __align__(16) char smraw[];
    uint32_t sb   = smem_u32(smraw);
    uint32_t qs_b = sb + K3_QS;
    uint32_t ks_b = sb + K3_KS;
    uint32_t vs_b = sb + K3_VS;

    int bh = blockIdx.x;
    int b = bh >> 7, h = bh & 127;
    const __half* Qg = g_qkv + (size_t)b * CHWn + (size_t)h * Wn;  // [c][w]
    const __half* Kg = Qg + IMG;
    const __half* Vg = Qg + 2 * IMG;
    float* Og = out + (size_t)b * CHWn + (size_t)h * Wn;

    int tid = threadIdx.x;
    int lane = tid & 31, warp = tid >> 5;
    int g = lane >> 2, tg = lane & 3;
    int m0 = warp * 16;

    int qRow  = m0 + (lane & 15);
    int qKoff = (lane >> 4) * 8;
    int kOff  = ((lane >> 4) & 1) * 8 + (lane & 7);
    int kKoff = ((lane >> 3) & 1) * 8;
    int vRow  = lane & 15;
    int vCol8 = (lane >> 4) * 8;

    #pragma unroll
    for (int i = 0; i < 8; i++) {
        int chunk = tid + i * 512;
        int row = chunk >> 4, col = (chunk & 15) * 8;
        cp16(qs_b + (row * 136 + col) * 2, Qg + (size_t)row * HWn + col);
        cp16(ks_b + (row * 136 + col) * 2, Kg + (size_t)row * HWn + col);
    }
    CP_COMMIT();
    #pragma unroll
    for (int i = 0; i < 8; i++) {
        int chunk = tid + i * 512;
        int row = chunk >> 4, col = (chunk & 15) * 8;
        cp16(vs_b + (row * 136 + col) * 2, Vg + (size_t)row * HWn + col);
    }
    CP_COMMIT();
    CP_WAIT1();
    __syncthreads();

    float O[16][4];
    #pragma unroll
    for (int i = 0; i < 16; i++)
        #pragma unroll
        for (int r = 0; r < 4; r++) O[i][r] = 0.f;
    float mrow0 = -1e30f, mrow1 = -1e30f;
    float lrow0 = 0.f,    lrow1 = 0.f;

    #pragma unroll 1
    for (int db = 0; db < 4; db++) {
        int d0 = db * 64;

        float S[8][4];
        #pragma unroll
        for (int i = 0; i < 8; i++)
            #pragma unroll
            for (int r = 0; r < 4; r++) S[i][r] = 0.f;

        #pragma unroll
        for (int kc = 0; kc < 8; kc++) {
            int k0 = kc * 16;
            uint32_t aq[4], bf[8][2];
            ldsm4(aq[0], aq[1], aq[2], aq[3],
                  qs_b + (qRow * 136 + k0 + qKoff) * 2);
            #pragma unroll
            for (int j = 0; j < 4; j++)
                ldsm4(bf[2 * j][0], bf[2 * j][1], bf[2 * j + 1][0], bf[2 * j + 1][1],
                      ks_b + ((d0 + j * 16 + kOff) * 136 + k0 + kKoff) * 2);
            #pragma unroll
            for (int nb = 0; nb < 8; nb++)
                mma16(S[nb], aq, bf[nb]);
        }

        float bm0 = -1e30f, bm1 = -1e30f;
        #pragma unroll
        for (int nb = 0; nb < 8; nb++) {
            bm0 = fmaxf(bm0, fmaxf(S[nb][0], S[nb][1]));
            bm1 = fmaxf(bm1, fmaxf(S[nb][2], S[nb][3]));
        }
        #pragma unroll
        for (int o = 1; o <= 2; o <<= 1) {
            bm0 = fmaxf(bm0, __shfl_xor_sync(0xffffffffu, bm0, o));
            bm1 = fmaxf(bm1, __shfl_xor_sync(0xffffffffu, bm1, o));
        }
        float mn0 = fmaxf(mrow0, bm0), mn1 = fmaxf(mrow1, bm1);
        float corr0 = __expf(mrow0 - mn0), corr1 = __expf(mrow1 - mn1);
        mrow0 = mn0; mrow1 = mn1;

        float bs0 = 0.f, bs1 = 0.f;
        #pragma unroll
        for (int nb = 0; nb < 8; nb++) {
            S[nb][0] = __expf(S[nb][0] - mn0);
            S[nb][1] = __expf(S[nb][1] - mn0);
            S[nb][2] = __expf(S[nb][2] - mn1);
            S[nb][3] = __expf(S[nb][3] - mn1);
            bs0 += S[nb][0] + S[nb][1];
            bs1 += S[nb][2] + S[nb][3];
        }
        #pragma unroll
        for (int o = 1; o <= 2; o <<= 1) {
            bs0 += __shfl_xor_sync(0xffffffffu, bs0, o);
            bs1 += __shfl_xor_sync(0xffffffffu, bs1, o);
        }
        lrow0 = lrow0 * corr0 + bs0;
        lrow1 = lrow1 * corr1 + bs1;
        #pragma unroll
        for (int i = 0; i < 16; i++) {
            O[i][0] *= corr0; O[i][1] *= corr0;
            O[i][2] *= corr1; O[i][3] *= corr1;
        }

        if (db == 0) { CP_WAIT0(); __syncthreads(); }

        #pragma unroll
        for (int kc = 0; kc < 4; kc++) {
            uint32_t pa[4];
            pa[0] = f2h2(S[2 * kc][0],     S[2 * kc][1]);
            pa[1] = f2h2(S[2 * kc][2],     S[2 * kc][3]);
            pa[2] = f2h2(S[2 * kc + 1][0], S[2 * kc + 1][1]);
            pa[3] = f2h2(S[2 * kc + 1][2], S[2 * kc + 1][3]);
            int dr = d0 + kc * 16 + vRow;
            #pragma unroll
            for (int nv = 0; nv < 8; nv++) {
                uint32_t bv[4];
                ldsm4t(bv[0], bv[1], bv[2], bv[3],
                       vs_b + (dr * 136 + nv * 16 + vCol8) * 2);
                uint32_t b0[2] = {bv[0], bv[1]};
                uint32_t b1[2] = {bv[2], bv[3]};
                mma16(O[2 * nv],     pa, b0);
                mma16(O[2 * nv + 1], pa, b1);
            }
        }
    }

    float inv0 = 1.f / lrow0, inv1 = 1.f / lrow1;
    int r0 = m0 + g, r1 = m0 + 8 + g;
    #pragma unroll
    for (int nv = 0; nv < 16; nv++) {
        int n = nv * 8 + tg * 2;
        *(float2*)(Og + (size_t)r0 * HWn + n) =
            make_float2(O[nv][0] * inv0, O[nv][1] * inv0);
        *(float2*)(Og + (size_t)r1 * HWn + n) =
            make_float2(O[nv][2] * inv1, O[nv][3] * inv1);
    }
}

// ---------------------------------------------------------------------------
extern "C" void kernel_launch(void* const* d_in, const int* in_sizes, int n_in,
                              void* d_out, int out_size)
{
    (void)in_sizes; (void)n_in; (void)out_size;
    const float* hidden = (const float*)d_in[0];
    const float* ctx    = (const float*)d_in[1];
    const float* qdw = (const float*)d_in[2];
    const float* qdb = (const float*)d_in[3];
    const float* qpw = (const float*)d_in[4];
    const float* qpb = (const float*)d_in[5];
    const float* kdw = (const float*)d_in[6];
    const float* kdb = (const float*)d_in[7];
    const float* kpw = (const float*)d_in[8];
    const float* kpb = (const float*)d_in[9];
    const float* vdw = (const float*)d_in[10];
    const float* vdb = (const float*)d_in[11];
    const float* vpw = (const float*)d_in[12];
    const float* vpb = (const float*)d_in[13];
    float* out = (float*)d_out;

    k_wconv<<<dim3(128, 3), 256>>>(qpw, kpw, vpw);
    k_dwconv<<<dim3(Hn / 32, Bn * Cn), 256>>>(hidden, ctx, qdw, qdb, kdw, kdb, vdw, vdb);

    cudaFuncSetAttribute(k_pointwise, cudaFuncAttributeMaxDynamicSharedMemorySize, PW_SMEM);
    k_pointwise<<<dim3(HWn / 64, 24), 256, PW_SMEM>>>(qpb, kpb, vpb);

    cudaFuncSetAttribute(k_attn, cudaFuncAttributeMaxDynamicSharedMemorySize, K3_SMEM);
    k_attn<<<Bn * Hn, 512, K3_SMEM>>>(out);
}

// round 16
// speedup vs baseline: 1.0542x; 1.0542x over previous
#include <cuda_runtime.h>
#include <cuda_fp16.h>
#include <cstdint>
#include <cstddef>

// ---------------------------------------------------------------------------
// CrossAttention_41497974014052  (sm_103a, legacy mma path)
// K0: W fp32 -> half pre-convert
// K1: depthwise3x3 (smem-tiled, 32-row tiles, half2 stores)
// K2: pointwise GEMM, CTA tile 256(M)x128(N), 512 thr (16 warps 4Mx4N),
//     y read ONCE, fp16 m16n8k16, cp.async 3-stage, ldmatrix frags
// K3: per-(b,h) channel attention, FA2-style (unchanged from R13)
// ---------------------------------------------------------------------------

constexpr int Bn = 8, Cn = 256, Hn = 128, Wn = 128;
constexpr int HWn = Hn * Wn;                    // 16384
constexpr size_t CHWn = (size_t)Cn * HWn;       // 4194304
constexpr size_t IMG  = (size_t)Bn * CHWn;      // 33554432

__device__ __half g_y[3 * IMG];
__device__ __half g_qkv[3 * IMG];
__device__ __half g_wh[3 * 65536];

__device__ __forceinline__ uint32_t f2h2(float a, float b) {
    __half2 h = __floats2half2_rn(a, b);
    return *reinterpret_cast<uint32_t*>(&h);
}
__device__ __forceinline__ uint32_t smem_u32(const void* p) {
    uint32_t a;
    asm("{ .reg .u64 t; cvta.to.shared.u64 t, %1; cvt.u32.u64 %0, t; }" : "=r"(a) : "l"(p));
    return a;
}
__device__ __forceinline__ void mma16(float d[4], const uint32_t a[4], const uint32_t b[2]) {
    asm volatile(
        "mma.sync.aligned.m16n8k16.row.col.f32.f16.f16.f32 "
        "{%0,%1,%2,%3}, {%4,%5,%6,%7}, {%8,%9}, {%0,%1,%2,%3};\n"
        : "+f"(d[0]), "+f"(d[1]), "+f"(d[2]), "+f"(d[3])
        : "r"(a[0]), "r"(a[1]), "r"(a[2]), "r"(a[3]), "r"(b[0]), "r"(b[1]));
}
__device__ __forceinline__ void ldsm4(uint32_t& r0, uint32_t& r1, uint32_t& r2, uint32_t& r3,
                                      uint32_t addr) {
    asm volatile("ldmatrix.sync.aligned.m8n8.x4.shared.b16 {%0,%1,%2,%3}, [%4];"
                 : "=r"(r0), "=r"(r1), "=r"(r2), "=r"(r3) : "r"(addr));
}
__device__ __forceinline__ void ldsm4t(uint32_t& r0, uint32_t& r1, uint32_t& r2, uint32_t& r3,
                                       uint32_t addr) {
    asm volatile("ldmatrix.sync.aligned.m8n8.x4.trans.shared.b16 {%0,%1,%2,%3}, [%4];"
                 : "=r"(r0), "=r"(r1), "=r"(r2), "=r"(r3) : "r"(addr));
}
__device__ __forceinline__ void cp16(uint32_t dst, const void* src) {
    asm volatile("cp.async.cg.shared.global [%0], [%1], 16;"
                 :: "r"(dst), "l"((size_t)__cvta_generic_to_global(src)) : "memory");
}
#define CP_COMMIT() asm volatile("cp.async.commit_group;" ::: "memory")
#define CP_WAIT1()  asm volatile("cp.async.wait_group 1;" ::: "memory")
#define CP_WAIT0()  asm volatile("cp.async.wait_group 0;" ::: "memory")

// ---------------------------------------------------------------------------
// Kernel 0: W fp32 -> half. grid (128, 3), 256 thr.
// ---------------------------------------------------------------------------
__global__ void k_wconv(const float* __restrict__ qpw, const float* __restrict__ kpw,
                        const float* __restrict__ vpw)
{
    int t = blockIdx.y;
    const float* W = (t == 0) ? qpw : (t == 1) ? kpw : vpw;
    int i = (blockIdx.x * 256 + threadIdx.x) * 2;
    float2 v = *(const float2*)(W + i);
    *(__half2*)(g_wh + t * 65536 + i) = __floats2half2_rn(v.x, v.y);
}

// ---------------------------------------------------------------------------
// Kernel 1: depthwise 3x3 (SAME) + bias, smem-tiled, 32-row tiles,
// 2 cols/thread (half2 out). grid (H/32, B*C), 256 threads.
// ---------------------------------------------------------------------------
__global__ void __launch_bounds__(256)
k_dwconv(const float* __restrict__ hidden, const float* __restrict__ ctx,
         const float* __restrict__ qw, const float* __restrict__ qb,
         const float* __restrict__ kw, const float* __restrict__ kb,
         const float* __restrict__ vw, const float* __restrict__ vb)
{
    __shared__ float shH[34][132];
    __shared__ float shC[34][132];

    int h0 = blockIdx.x * 32;
    int bc = blockIdx.y;
    int c  = bc & (Cn - 1);
    int tid = threadIdx.x;
    size_t base = (size_t)bc * HWn;
    const float* xh = hidden + base;
    const float* xc = ctx + base;

    for (int idx = tid; idx < 34 * 130; idx += 256) {
        int r = idx / 130, ci = idx - r * 130;
        int hh = h0 + r - 1, ww = ci - 1;
        bool ok = ((unsigned)hh < (unsigned)Hn) & ((unsigned)ww < (unsigned)Wn);
        float vh = 0.f, vc = 0.f;
        if (ok) { int o = hh * Wn + ww; vh = xh[o]; vc = xc[o]; }
        shH[r][ci] = vh;
        shC[r][ci] = vc;
    }

    float wq[9], wk[9], wv[9];
    #pragma unroll
    for (int i = 0; i < 9; i++) {
        wq[i] = qw[c * 9 + i]; wk[i] = kw[c * 9 + i]; wv[i] = vw[c * 9 + i];
    }
    float bq = qb[c], bk = kb[c], bv = vb[c];
    __syncthreads();

    int w2 = (tid & 63) * 2;
    int rb = (tid >> 6) * 8;          // 4 groups x 8 rows = 32 rows

    float A0[4], A1[4], A2[4], B0[4], B1[4], B2[4];
    #pragma unroll
    for (int j = 0; j < 4; j++) {
        A0[j] = shH[rb][w2 + j];     A1[j] = shH[rb + 1][w2 + j];
        B0[j] = shC[rb][w2 + j];     B1[j] = shC[rb + 1][w2 + j];
    }

    #pragma unroll
    for (int rr = 0; rr < 8; rr++) {
        #pragma unroll
        for (int j = 0; j < 4; j++) {
            A2[j] = shH[rb + rr + 2][w2 + j];
            B2[j] = shC[rb + rr + 2][w2 + j];
        }
        float aq0 = bq, aq1 = bq, ak0 = bk, ak1 = bk, av0 = bv, av1 = bv;
        #pragma unroll
        for (int j = 0; j < 3; j++) {
            aq0 += wq[j] * A0[j]     + wq[3 + j] * A1[j]     + wq[6 + j] * A2[j];
            aq1 += wq[j] * A0[j + 1] + wq[3 + j] * A1[j + 1] + wq[6 + j] * A2[j + 1];
            ak0 += wk[j] * B0[j]     + wk[3 + j] * B1[j]     + wk[6 + j] * B2[j];
            ak1 += wk[j] * B0[j + 1] + wk[3 + j] * B1[j + 1] + wk[6 + j] * B2[j + 1];
            av0 += wv[j] * B0[j]     + wv[3 + j] * B1[j]     + wv[6 + j] * B2[j];
            av1 += wv[j] * B0[j + 1] + wv[3 + j] * B1[j + 1] + wv[6 + j] * B2[j + 1];
        }
        size_t o = base + (size_t)(h0 + rb + rr) * Wn + w2;
        *(__half2*)(g_y + o)           = __floats2half2_rn(aq0, aq1);
        *(__half2*)(g_y + IMG + o)     = __floats2half2_rn(ak0, ak1);
        *(__half2*)(g_y + 2 * IMG + o) = __floats2half2_rn(av0, av1);
        #pragma unroll
        for (int j = 0; j < 4; j++) {
            A0[j] = A1[j]; A1[j] = A2[j];
            B0[j] = B1[j]; B1[j] = B2[j];
        }
    }
}

// ---------------------------------------------------------------------------
// Kernel 2: pointwise GEMM  D[o][s] = sum_c W[o][c] * y[c][s] + bias[o]
// CTA tile 256(M) x 128(N), 512 thr = 16 warps (4M x 4N), warp tile 64x32.
// y streamed ONCE (M covers all output channels). fp16 m16n8k16,
// K=256 in 8 chunks of 32, cp.async 3-stage, ldmatrix frags.
// q output (t==0) pre-scaled by 1/sqrt(32).
// grid (128, 24), 1 CTA/SM.
// ---------------------------------------------------------------------------
constexpr int PW_AS_STRIDE = 256 * 40 * 2;   // 20480
constexpr int PW_BS_BASE   = 3 * PW_AS_STRIDE;              // 61440
constexpr int PW_BS_STRIDE = 32 * 136 * 2;   // 8704
constexpr int PW_SMEM      = PW_BS_BASE + 3 * PW_BS_STRIDE; // 87552

__global__ void __launch_bounds__(512, 1)
k_pointwise(const float* __restrict__ qpb, const float* __restrict__ kpb,
            const float* __restrict__ vpb)
{
    extern __shared__ __align__(16) char dyn[];
    uint32_t sb = smem_u32(dyn);

    int nt = blockIdx.x, tb = blockIdx.y;
    int t = tb >> 3, b = tb & 7;
    const float* bias = (t == 0) ? qpb : (t == 1) ? kpb : vpb;
    const float oscale = (t == 0) ? 0.17677669529663687f : 1.0f;
    const __half* Wh = g_wh + t * 65536;
    const __half* Yt = g_y  + (size_t)t * IMG + (size_t)b * CHWn;
    __half*       Cm = g_qkv + (size_t)t * IMG + (size_t)b * CHWn;
    int n0 = nt * 128;

    int tid = threadIdx.x, lane = tid & 31, warp = tid >> 5;
    int wm = warp >> 2, wn = warp & 3, g = lane >> 2, tg = lane & 3;

    int rA = tid >> 1, cA = (tid & 1) * 16;   // A: 256 rows x 32 k-cols
    int rB = tid >> 4, cB = (tid & 15) * 8;   // B: 32 rows x 128 cols

    int aRow = wm * 64 + (lane & 15);
    int aKoff = (lane >> 4) * 8;

    auto issue = [&](int stage) {
        int buf = stage % 3;
        int k0 = stage * 32;
        uint32_t asb = sb + buf * PW_AS_STRIDE;
        uint32_t bsb = sb + PW_BS_BASE + buf * PW_BS_STRIDE;
        const __half* srcA = Wh + (size_t)rA * Cn + k0 + cA;
        cp16(asb + (rA * 40 + cA) * 2, srcA);
        cp16(asb + (rA * 40 + cA + 8) * 2, srcA + 8);
        cp16(bsb + (rB * 136 + cB) * 2, Yt + (size_t)(k0 + rB) * HWn + n0 + cB);
        CP_COMMIT();
    };

    float acc[4][4][4];
    #pragma unroll
    for (int i = 0; i < 4; i++)
        #pragma unroll
        for (int j = 0; j < 4; j++)
            #pragma unroll
            for (int r = 0; r < 4; r++) acc[i][j][r] = 0.f;

    issue(0);
    issue(1);

    for (int kc = 0; kc < 8; kc++) {
        if (kc < 7) { CP_WAIT1(); } else { CP_WAIT0(); }
        __syncthreads();
        if (kc + 2 < 8) issue(kc + 2);

        int buf = kc % 3;
        uint32_t asb = sb + buf * PW_AS_STRIDE;
        uint32_t bsb = sb + PW_BS_BASE + buf * PW_BS_STRIDE;

        #pragma unroll
        for (int kk = 0; kk < 32; kk += 16) {
            uint32_t af[4][4], bfm[4][2];
            #pragma unroll
            for (int mi = 0; mi < 4; mi++)
                ldsm4(af[mi][0], af[mi][1], af[mi][2], af[mi][3],
                      asb + ((aRow + mi * 16) * 40 + kk + aKoff) * 2);
            #pragma unroll
            for (int nh = 0; nh < 2; nh++) {
                int lrow = kk + (lane & 15);
                int lcol = wn * 32 + nh * 16 + (lane >> 4) * 8;
                ldsm4t(bfm[2 * nh][0], bfm[2 * nh][1], bfm[2 * nh + 1][0], bfm[2 * nh + 1][1],
                       bsb + (lrow * 136 + lcol) * 2);
            }
            #pragma unroll
            for (int mi = 0; mi < 4; mi++)
                #pragma unroll
                for (int nb = 0; nb < 4; nb++)
                    mma16(acc[mi][nb], af[mi], bfm[nb]);
        }
    }

    #pragma unroll
    for (int mi = 0; mi < 4; mi++) {
        int m = wm * 64 + mi * 16 + g;
        float b0v = bias[m], b1v = bias[m + 8];
        #pragma unroll
        for (int nb = 0; nb < 4; nb++) {
            int n = n0 + wn * 32 + nb * 8 + tg * 2;
            *(__half2*)(Cm + (size_t)m * HWn + n) =
                __floats2half2_rn((acc[mi][nb][0] + b0v) * oscale, (acc[mi][nb][1] + b0v) * oscale);
            *(__half2*)(Cm + (size_t)(m + 8) * HWn + n) =
                __floats2half2_rn((acc[mi][nb][2] + b1v) * oscale, (acc[mi][nb][3] + b1v) * oscale);
        }
    }
}

// ---------------------------------------------------------------------------
// Kernel 3: per-(b,h) channel attention, FA2-style (unchanged from R13).
// 512 threads = 16 warps; warp w owns S-rows [16w, 16w+16).
// smem: Qs 256x136 | Ks 256x136 | Vs 256x136 (half)  = 208896 B
// ---------------------------------------------------------------------------
constexpr int K3_QS   = 0;
constexpr int K3_KS   = 256 * 136 * 2;            // 69632
constexpr int K3_VS   = 2 * 256 * 136 * 2;        // 139264
constexpr int K3_SMEM = 3 * 256 * 136 * 2;        // 208896

__global__ void __launch_bounds__(512)
k_attn(float* __restrict__ out)
{
    extern __shared__ __align__(16) char smraw[];
    uint32_t sb   = smem_u32(smraw);
    uint32_t qs_b = sb + K3_QS;
    uint32_t ks_b = sb + K3_KS;
    uint32_t vs_b = sb + K3_VS;

    int bh = blockIdx.x;
    int b = bh >> 7, h = bh & 127;
    const __half* Qg = g_qkv + (size_t)b * CHWn + (size_t)h * Wn;  // [c][w]
    const __half* Kg = Qg + IMG;
    const __half* Vg = Qg + 2 * IMG;
    float* Og = out + (size_t)b * CHWn + (size_t)h * Wn;

    int tid = threadIdx.x;
    int lane = tid & 31, warp = tid >> 5;
    int g = lane >> 2, tg = lane & 3;
    int m0 = warp * 16;

    int qRow  = m0 + (lane & 15);
    int qKoff = (lane >> 4) * 8;
    int kOff  = ((lane >> 4) & 1) * 8 + (lane & 7);
    int kKoff = ((lane >> 3) & 1) * 8;
    int vRow  = lane & 15;
    int vCol8 = (lane >> 4) * 8;

    #pragma unroll
    for (int i = 0; i < 8; i++) {
        int chunk = tid + i * 512;
        int row = chunk >> 4, col = (chunk & 15) * 8;
        cp16(qs_b + (row * 136 + col) * 2, Qg + (size_t)row * HWn + col);
        cp16(ks_b + (row * 136 + col) * 2, Kg + (size_t)row * HWn + col);
    }
    CP_COMMIT();
    #pragma unroll
    for (int i = 0; i < 8; i++) {
        int chunk = tid + i * 512;
        int row = chunk >> 4, col = (chunk & 15) * 8;
        cp16(vs_b + (row * 136 + col) * 2, Vg + (size_t)row * HWn + col);
    }
    CP_COMMIT();
    CP_WAIT1();
    __syncthreads();

    float O[16][4];
    #pragma unroll
    for (int i = 0; i < 16; i++)
        #pragma unroll
        for (int r = 0; r < 4; r++) O[i][r] = 0.f;
    float mrow0 = -1e30f, mrow1 = -1e30f;
    float lrow0 = 0.f,    lrow1 = 0.f;

    #pragma unroll 1
    for (int db = 0; db < 4; db++) {
        int d0 = db * 64;

        float S[8][4];
        #pragma unroll
        for (int i = 0; i < 8; i++)
            #pragma unroll
            for (int r = 0; r < 4; r++) S[i][r] = 0.f;

        #pragma unroll
        for (int kc = 0; kc < 8; kc++) {
            int k0 = kc * 16;
            uint32_t aq[4], bf[8][2];
            ldsm4(aq[0], aq[1], aq[2], aq[3],
                  qs_b + (qRow * 136 + k0 + qKoff) * 2);
            #pragma unroll
            for (int j = 0; j < 4; j++)
                ldsm4(bf[2 * j][0], bf[2 * j][1], bf[2 * j + 1][0], bf[2 * j + 1][1],
                      ks_b + ((d0 + j * 16 + kOff) * 136 + k0 + kKoff) * 2);
            #pragma unroll
            for (int nb = 0; nb < 8; nb++)
                mma16(S[nb], aq, bf[nb]);
        }

        float bm0 = -1e30f, bm1 = -1e30f;
        #pragma unroll
        for (int nb = 0; nb < 8; nb++) {
            bm0 = fmaxf(bm0, fmaxf(S[nb][0], S[nb][1]));
            bm1 = fmaxf(bm1, fmaxf(S[nb][2], S[nb][3]));
        }
        #pragma unroll
        for (int o = 1; o <= 2; o <<= 1) {
            bm0 = fmaxf(bm0, __shfl_xor_sync(0xffffffffu, bm0, o));
            bm1 = fmaxf(bm1, __shfl_xor_sync(0xffffffffu, bm1, o));
        }
        float mn0 = fmaxf(mrow0, bm0), mn1 = fmaxf(mrow1, bm1);
        float corr0 = __expf(mrow0 - mn0), corr1 = __expf(mrow1 - mn1);
        mrow0 = mn0; mrow1 = mn1;

        float bs0 = 0.f, bs1 = 0.f;
        #pragma unroll
        for (int nb = 0; nb < 8; nb++) {
            S[nb][0] = __expf(S[nb][0] - mn0);
            S[nb][1] = __expf(S[nb][1] - mn0);
            S[nb][2] = __expf(S[nb][2] - mn1);
            S[nb][3] = __expf(S[nb][3] - mn1);
            bs0 += S[nb][0] + S[nb][1];
            bs1 += S[nb][2] + S[nb][3];
        }
        #pragma unroll
        for (int o = 1; o <= 2; o <<= 1) {
            bs0 += __shfl_xor_sync(0xffffffffu, bs0, o);
            bs1 += __shfl_xor_sync(0xffffffffu, bs1, o);
        }
        lrow0 = lrow0 * corr0 + bs0;
        lrow1 = lrow1 * corr1 + bs1;
        #pragma unroll
        for (int i = 0; i < 16; i++) {
            O[i][0] *= corr0; O[i][1] *= corr0;
            O[i][2] *= corr1; O[i][3] *= corr1;
        }

        if (db == 0) { CP_WAIT0(); __syncthreads(); }

        #pragma unroll
        for (int kc = 0; kc < 4; kc++) {
            uint32_t pa[4];
            pa[0] = f2h2(S[2 * kc][0],     S[2 * kc][1]);
            pa[1] = f2h2(S[2 * kc][2],     S[2 * kc][3]);
            pa[2] = f2h2(S[2 * kc + 1][0], S[2 * kc + 1][1]);
            pa[3] = f2h2(S[2 * kc + 1][2], S[2 * kc + 1][3]);
            int dr = d0 + kc * 16 + vRow;
            #pragma unroll
            for (int nv = 0; nv < 8; nv++) {
                uint32_t bv[4];
                ldsm4t(bv[0], bv[1], bv[2], bv[3],
                       vs_b + (dr * 136 + nv * 16 + vCol8) * 2);
                uint32_t b0[2] = {bv[0], bv[1]};
                uint32_t b1[2] = {bv[2], bv[3]};
                mma16(O[2 * nv],     pa, b0);
                mma16(O[2 * nv + 1], pa, b1);
            }
        }
    }

    float inv0 = 1.f / lrow0, inv1 = 1.f / lrow1;
    int r0 = m0 + g, r1 = m0 + 8 + g;
    #pragma unroll
    for (int nv = 0; nv < 16; nv++) {
        int n = nv * 8 + tg * 2;
        *(float2*)(Og + (size_t)r0 * HWn + n) =
            make_float2(O[nv][0] * inv0, O[nv][1] * inv0);
        *(float2*)(Og + (size_t)r1 * HWn + n) =
            make_float2(O[nv][2] * inv1, O[nv][3] * inv1);
    }
}

// ---------------------------------------------------------------------------
extern "C" void kernel_launch(void* const* d_in, const int* in_sizes, int n_in,
                              void* d_out, int out_size)
{
    (void)in_sizes; (void)n_in; (void)out_size;
    const float* hidden = (const float*)d_in[0];
    const float* ctx    = (const float*)d_in[1];
    const float* qdw = (const float*)d_in[2];
    const float* qdb = (const float*)d_in[3];
    const float* qpw = (const float*)d_in[4];
    const float* qpb = (const float*)d_in[5];
    const float* kdw = (const float*)d_in[6];
    const float* kdb = (const float*)d_in[7];
    const float* kpw = (const float*)d_in[8];
    const float* kpb = (const float*)d_in[9];
    const float* vdw = (const float*)d_in[10];
    const float* vdb = (const float*)d_in[11];
    const float* vpw = (const float*)d_in[12];
    const float* vpb = (const float*)d_in[13];
    float* out = (float*)d_out;

    k_wconv<<<dim3(128, 3), 256>>>(qpw, kpw, vpw);
    k_dwconv<<<dim3(Hn / 32, Bn * Cn), 256>>>(hidden, ctx, qdw, qdb, kdw, kdb, vdw, vdb);

    cudaFuncSetAttribute(k_pointwise, cudaFuncAttributeMaxDynamicSharedMemorySize, PW_SMEM);
    k_pointwise<<<dim3(HWn / 128, 24), 512, PW_SMEM>>>(qpb, kpb, vpb);

    cudaFuncSetAttribute(k_attn, cudaFuncAttributeMaxDynamicSharedMemorySize, K3_SMEM);
    k_attn<<<Bn * Hn, 512, K3_SMEM>>>(out);
}